// round 1
// baseline (speedup 1.0000x reference)
#include <cuda_runtime.h>
#include <math.h>

#define BB 16
#define TT 32
#define NRE (3*512)

__constant__ float c_anch[18] = {
    10.f/8.f, 13.f/8.f, 16.f/8.f, 30.f/8.f, 33.f/8.f, 23.f/8.f,
    30.f/16.f, 61.f/16.f, 62.f/16.f, 45.f/16.f, 59.f/16.f, 119.f/16.f,
    116.f/32.f, 90.f/32.f, 156.f/32.f, 198.f/32.f, 373.f/32.f, 326.f/32.f
};

// per-scale accumulators: [s*8+0]=box_base [1]=sp_base [2]=box_delta
//                         [3]=obj_sum [4]=noobj_sub [5]=cls_sum
__device__ float g_acc[24];
__device__ int   g_nobj[3];
__device__ int   g_rvalid[NRE];
__device__ int   g_rgy[NRE], g_rgx[NRE], g_rba[NRE], g_rcls[NRE];
__device__ float g_rtb[NRE * 4];

__device__ __forceinline__ float sp(float x) {
    // matches max(x,0) + log1p(exp(-|x|))
    return fmaxf(x, 0.f) + log1pf(expf(-fabsf(x)));
}

__device__ __forceinline__ float warp_sum(float v) {
    #pragma unroll
    for (int o = 16; o; o >>= 1) v += __shfl_down_sync(0xffffffffu, v, o);
    return v;
}

__global__ void prep_kernel(const float* __restrict__ targets) {
    const int s = blockIdx.x;          // scale 0..2
    const int tid = threadIdx.x;       // 0..511 == b*32 + t
    const int b = tid >> 5, t = tid & 31;
    const int Wd[3] = {80, 40, 20};
    const int W = Wd[s], H = W;

    // zero this scale's accumulators (before any atomics below)
    if (tid < 8) g_acc[s * 8 + tid] = 0.f;
    if (tid == 8) g_nobj[s] = 0;

    const float* tg = targets + (size_t)(b * TT + t) * 5;
    const float cls = tg[0], tx = tg[1], ty = tg[2], tw = tg[3], th = tg[4];

    int gx = (int)floorf(tx * (float)W); gx = min(max(gx, 0), W - 1);
    int gy = (int)floorf(ty * (float)H); gy = min(max(gy, 0), H - 1);

    float best = -1.f; int ba = 0;
    #pragma unroll
    for (int a = 0; a < 3; a++) {
        const float aw = c_anch[s * 6 + a * 2], ah = c_anch[s * 6 + a * 2 + 1];
        const float inter = fminf(tw, aw) * fminf(th, ah);
        const float iou = inter / (tw * th + aw * ah - inter + 1e-6f);
        if (iou > best) { best = iou; ba = a; }   // first-max wins
    }
    int valid = (best > 0.3f) ? 1 : 0;
    const int lin = (gy * W + gx) * 3 + ba;

    __shared__ int s_lin[512];
    __shared__ int s_val[512];
    s_lin[tid] = lin; s_val[tid] = valid;
    __syncthreads();

    int shadowed = 0;
    for (int t2 = t + 1; t2 < TT; t2++) {
        const int i2 = (b << 5) | t2;
        if (s_lin[i2] == lin && s_val[i2]) shadowed = 1;
    }
    valid = valid && !shadowed;

    const int rec = s * 512 + tid;
    g_rvalid[rec] = valid;
    if (valid) {
        atomicAdd(&g_nobj[s], 1);
        const float aw = c_anch[s * 6 + ba * 2], ah = c_anch[s * 6 + ba * 2 + 1];
        g_rgy[rec] = gy; g_rgx[rec] = gx; g_rba[rec] = ba; g_rcls[rec] = (int)cls;
        g_rtb[rec * 4 + 0] = tx * (float)W - (float)gx;
        g_rtb[rec * 4 + 1] = ty * (float)H - (float)gy;
        g_rtb[rec * 4 + 2] = logf(tw / aw + 1e-6f);
        g_rtb[rec * 4 + 3] = logf(th / ah + 1e-6f);
    }
}

// dense pass over the 15 relevant channels per (b, anchor): j=0..3 -> sum p^2, j=4 -> sum softplus
__global__ void base_kernel(const float* __restrict__ p, int HW, int scale) {
    const int HW4 = HW >> 2;
    const int nv = BB * 15 * HW4;
    float bacc = 0.f, sacc = 0.f;
    for (int i = blockIdx.x * blockDim.x + threadIdx.x; i < nv;
         i += gridDim.x * blockDim.x) {
        const int row = i / HW4;        // b*15 + k
        const int col = i - row * HW4;
        const int bidx = row / 15;
        const int k = row - bidx * 15;
        const int a = k / 5, j = k - a * 5;
        const float4 v = reinterpret_cast<const float4*>(
            p + (size_t)(bidx * 75 + a * 25 + j) * HW)[col];
        if (j < 4) {
            bacc += v.x * v.x + v.y * v.y + v.z * v.z + v.w * v.w;
        } else {
            sacc += sp(v.x) + sp(v.y) + sp(v.z) + sp(v.w);
        }
    }
    // block reduce (2 values)
    __shared__ float sh[2][8];
    const int lane = threadIdx.x & 31, wid = threadIdx.x >> 5;
    bacc = warp_sum(bacc); sacc = warp_sum(sacc);
    if (lane == 0) { sh[0][wid] = bacc; sh[1][wid] = sacc; }
    __syncthreads();
    if (wid == 0) {
        const int nw = blockDim.x >> 5;
        float b2 = (lane < nw) ? sh[0][lane] : 0.f;
        float s2 = (lane < nw) ? sh[1][lane] : 0.f;
        b2 = warp_sum(b2); s2 = warp_sum(s2);
        if (lane == 0) {
            atomicAdd(&g_acc[scale * 8 + 0], b2);
            atomicAdd(&g_acc[scale * 8 + 1], s2);
        }
    }
}

// one warp per target record: gather 25 channels at the target cell, compute corrections
__global__ void corr_kernel(const float* __restrict__ p0,
                            const float* __restrict__ p1,
                            const float* __restrict__ p2) {
    const int w = (blockIdx.x * blockDim.x + threadIdx.x) >> 5;
    const int lane = threadIdx.x & 31;
    if (w >= NRE) return;
    const int s = w / 512, r = w - s * 512, b = r >> 5;
    const int rec = s * 512 + r;
    if (!g_rvalid[rec]) return;

    const float* p = (s == 0) ? p0 : ((s == 1) ? p1 : p2);
    const int Wd[3] = {80, 40, 20};
    const int W = Wd[s], HW = W * W;
    const int gy = g_rgy[rec], gx = g_rgx[rec], ba = g_rba[rec], cls = g_rcls[rec];

    float bd = 0.f, os = 0.f, ns = 0.f, cs = 0.f;
    if (lane < 25) {
        const float x = p[(size_t)(b * 75 + ba * 25 + lane) * HW + gy * W + gx];
        if (lane < 4) {
            const float tb = g_rtb[rec * 4 + lane];
            bd = tb * tb - 2.f * x * tb;
        } else if (lane == 4) {
            os = sp(-x);   // bce(x,1) for obj cell
            ns = sp(x);    // remove from noobj base
        } else {
            cs = sp(x);
            if (lane - 5 == cls) cs -= x;   // softplus(x)-x == bce(x,1)
        }
    }
    bd = warp_sum(bd); os = warp_sum(os); ns = warp_sum(ns); cs = warp_sum(cs);
    if (lane == 0) {
        atomicAdd(&g_acc[s * 8 + 2], bd);
        atomicAdd(&g_acc[s * 8 + 3], os);
        atomicAdd(&g_acc[s * 8 + 4], ns);
        atomicAdd(&g_acc[s * 8 + 5], cs);
    }
}

__global__ void fin_kernel(float* __restrict__ out) {
    const int Wd[3] = {80, 40, 20};
    float total = 0.f;
    #pragma unroll
    for (int s = 0; s < 3; s++) {
        const float nobj_i = (float)g_nobj[s];
        const float cells = (float)(BB * Wd[s] * Wd[s] * 3);
        const float n_obj = nobj_i + 1e-6f;
        const float n_noobj = (cells - nobj_i) + 1e-6f;
        const float box_loss   = (g_acc[s * 8 + 0] + g_acc[s * 8 + 2]) / n_obj;
        const float obj_loss   =  g_acc[s * 8 + 3] / n_obj;
        const float noobj_loss = (g_acc[s * 8 + 1] - g_acc[s * 8 + 4]) / n_noobj;
        const float cls_loss   =  g_acc[s * 8 + 5] / n_obj;
        total += 0.05f * box_loss + 1.5f * (obj_loss + 0.5f * noobj_loss)
               + 0.15f * cls_loss;
    }
    out[0] = total;
}

extern "C" void kernel_launch(void* const* d_in, const int* in_sizes, int n_in,
                              void* d_out, int out_size) {
    const float* p0 = (const float*)d_in[0];
    const float* p1 = (const float*)d_in[1];
    const float* p2 = (const float*)d_in[2];
    const float* tg = (const float*)d_in[3];
    float* out = (float*)d_out;

    prep_kernel<<<3, 512>>>(tg);

    const int HW0 = 6400, HW1 = 1600, HW2 = 400;
    const int nv0 = BB * 15 * (HW0 >> 2);
    const int nv1 = BB * 15 * (HW1 >> 2);
    const int nv2 = BB * 15 * (HW2 >> 2);
    base_kernel<<<(nv0 + 255) / 256, 256>>>(p0, HW0, 0);
    base_kernel<<<(nv1 + 255) / 256, 256>>>(p1, HW1, 1);
    base_kernel<<<(nv2 + 255) / 256, 256>>>(p2, HW2, 2);

    corr_kernel<<<(NRE * 32 + 255) / 256, 256>>>(p0, p1, p2);
    fin_kernel<<<1, 1>>>(out);
}

// round 2
// speedup vs baseline: 1.8467x; 1.8467x over previous
#include <cuda_runtime.h>
#include <math.h>

#define BB 16
#define TT 32

__constant__ float c_anch[18] = {
    10.f/8.f, 13.f/8.f, 16.f/8.f, 30.f/8.f, 33.f/8.f, 23.f/8.f,
    30.f/16.f, 61.f/16.f, 62.f/16.f, 45.f/16.f, 59.f/16.f, 119.f/16.f,
    116.f/32.f, 90.f/32.f, 156.f/32.f, 198.f/32.f, 373.f/32.f, 326.f/32.f
};

// base kernel geometry: blocks of 256 threads, 1024 float4 per block
// scale0: 16*15*1600 = 384000 f4 -> 375 blocks (exact)
// scale1: 16*15*400  =  96000 f4 -> 94 blocks (bounds check)
// scale2: 16*15*100  =  24000 f4 -> 24 blocks (bounds check)
#define NB0 375
#define NB1 94
#define NB2 24
#define NBT (NB0 + NB1 + NB2)   // 493

// corr kernel: 48 blocks (16 per scale), 512 threads each
#define NCB 48

__device__ float g_bpart[NBT][2];   // per-block base partials: sum p^2, sum softplus
__device__ float g_cpart[NCB][5];   // per-block corr partials: bd, os, ns, cs, n_valid
__device__ int   g_ticket;          // zero-init; last block resets to 0

__device__ __forceinline__ float sp(float x) {
    return fmaxf(x, 0.f) + log1pf(expf(-fabsf(x)));
}

__device__ __forceinline__ float warp_sum(float v) {
    #pragma unroll
    for (int o = 16; o; o >>= 1) v += __shfl_down_sync(0xffffffffu, v, o);
    return v;
}

// ---------------------------------------------------------------------------
// K1: fused prep (per-scale target assignment) + corrections gather.
// 48 blocks x 512 threads. Block bid: scale s = bid>>4, gathers for batch
// b = bid&15 (records (bid&15)*32 .. +31). Each block redundantly computes
// the full prep for its scale (cheap), then its 16 warps each gather
// 2 records' 25 channels.
// ---------------------------------------------------------------------------
__global__ void prep_corr_kernel(const float* __restrict__ p0,
                                 const float* __restrict__ p1,
                                 const float* __restrict__ p2,
                                 const float* __restrict__ targets) {
    const int s   = blockIdx.x >> 4;     // scale
    const int blk = blockIdx.x & 15;     // batch this block's warps will gather
    const int tid = threadIdx.x;         // 0..511 = b*32 + t
    const int b = tid >> 5, t = tid & 31;
    const int Wd[3] = {80, 40, 20};
    const int W = Wd[s], HW = W * W;

    __shared__ int   s_lin[512];
    __shared__ int   s_val[512];     // pre-shadow validity
    __shared__ int   s_ok[512];      // post-shadow validity
    __shared__ int   s_meta[512];    // packed gy|gx|ba|cls
    __shared__ float s_tb[512][4];

    // ---- prep ----
    const float* tg = targets + (size_t)(b * TT + t) * 5;
    const float cls = tg[0], tx = tg[1], ty = tg[2], tw = tg[3], th = tg[4];

    int gx = (int)floorf(tx * (float)W); gx = min(max(gx, 0), W - 1);
    int gy = (int)floorf(ty * (float)W); gy = min(max(gy, 0), W - 1);

    float best = -1.f; int ba = 0;
    #pragma unroll
    for (int a = 0; a < 3; a++) {
        const float aw = c_anch[s * 6 + a * 2], ah = c_anch[s * 6 + a * 2 + 1];
        const float inter = fminf(tw, aw) * fminf(th, ah);
        const float iou = inter / (tw * th + aw * ah - inter + 1e-6f);
        if (iou > best) { best = iou; ba = a; }   // first-max wins
    }
    const int valid = (best > 0.3f) ? 1 : 0;
    const int lin = (gy * W + gx) * 3 + ba;

    s_lin[tid] = lin;
    s_val[tid] = valid;
    s_meta[tid] = (gy << 16) | (gx << 8) | (ba << 5) | (int)cls;
    {
        const float aw = c_anch[s * 6 + ba * 2], ah = c_anch[s * 6 + ba * 2 + 1];
        s_tb[tid][0] = tx * (float)W - (float)gx;
        s_tb[tid][1] = ty * (float)W - (float)gy;
        s_tb[tid][2] = logf(tw / aw + 1e-6f);
        s_tb[tid][3] = logf(th / ah + 1e-6f);
    }
    __syncthreads();

    int shadowed = 0;
    for (int t2 = t + 1; t2 < TT; t2++) {
        const int i2 = (b << 5) | t2;
        if (s_lin[i2] == lin && s_val[i2]) shadowed = 1;
    }
    s_ok[tid] = valid && !shadowed;
    __syncthreads();

    // ---- corr gather: this block handles batch blk (records blk*32..+31) ----
    const float* p = (s == 0) ? p0 : ((s == 1) ? p1 : p2);
    const int w = tid >> 5, lane = tid & 31;

    float bd = 0.f, os = 0.f, ns = 0.f, cs = 0.f, nv = 0.f;
    #pragma unroll
    for (int j = 0; j < 2; j++) {
        const int r = (blk << 5) + (w << 1) + j;    // shared index of record
        if (s_ok[r]) {
            nv += (lane == 0) ? 1.f : 0.f;
            const int m = s_meta[r];
            const int rgy = m >> 16, rgx = (m >> 8) & 0xff;
            const int rba = (m >> 5) & 3, rcls = m & 31;
            if (lane < 25) {
                const float x = p[(size_t)(blk * 75 + rba * 25 + lane) * HW
                                  + rgy * W + rgx];
                if (lane < 4) {
                    const float tb = s_tb[r][lane];
                    bd += tb * tb - 2.f * x * tb;
                } else if (lane == 4) {
                    os += sp(-x);
                    ns += sp(x);
                } else {
                    float c = sp(x);
                    if (lane - 5 == rcls) c -= x;
                    cs += c;
                }
            }
        }
    }
    bd = warp_sum(bd); os = warp_sum(os); ns = warp_sum(ns);
    cs = warp_sum(cs); nv = warp_sum(nv);

    __shared__ float red[16][5];
    if (lane == 0) {
        red[w][0] = bd; red[w][1] = os; red[w][2] = ns; red[w][3] = cs; red[w][4] = nv;
    }
    __syncthreads();
    if (tid == 0) {
        float a0 = 0, a1 = 0, a2 = 0, a3 = 0, a4 = 0;
        #pragma unroll
        for (int i = 0; i < 16; i++) {
            a0 += red[i][0]; a1 += red[i][1]; a2 += red[i][2];
            a3 += red[i][3]; a4 += red[i][4];
        }
        g_cpart[blockIdx.x][0] = a0; g_cpart[blockIdx.x][1] = a1;
        g_cpart[blockIdx.x][2] = a2; g_cpart[blockIdx.x][3] = a3;
        g_cpart[blockIdx.x][4] = a4;
    }
}

// ---------------------------------------------------------------------------
// K2: dense base pass (all 3 scales) + last-block final reduction
// ---------------------------------------------------------------------------
template<int HW4>
__device__ __forceinline__ void base_accum(const float* __restrict__ p, int e,
                                           float& bacc, float& sacc) {
    const int row = e / HW4;
    const int col = e - row * HW4;
    const int bidx = row / 15;
    const int k = row - bidx * 15;
    const int a = k / 5, j = k - a * 5;
    const float4 v = reinterpret_cast<const float4*>(p)
                        [(bidx * 75 + a * 25 + j) * HW4 + col];
    if (j < 4) {
        bacc += v.x * v.x + v.y * v.y + v.z * v.z + v.w * v.w;
    } else {
        sacc += sp(v.x) + sp(v.y) + sp(v.z) + sp(v.w);
    }
}

__global__ void base_fin_kernel(const float* __restrict__ p0,
                                const float* __restrict__ p1,
                                const float* __restrict__ p2,
                                float* __restrict__ out) {
    const int bid = blockIdx.x, tid = threadIdx.x;
    float bacc = 0.f, sacc = 0.f;

    if (bid < NB0) {
        const int base = bid * 1024 + tid;
        #pragma unroll
        for (int k = 0; k < 4; k++)
            base_accum<1600>(p0, base + k * 256, bacc, sacc);
    } else if (bid < NB0 + NB1) {
        const int base = (bid - NB0) * 1024 + tid;
        #pragma unroll
        for (int k = 0; k < 4; k++) {
            const int e = base + k * 256;
            if (e < 96000) base_accum<400>(p1, e, bacc, sacc);
        }
    } else {
        const int base = (bid - NB0 - NB1) * 1024 + tid;
        #pragma unroll
        for (int k = 0; k < 4; k++) {
            const int e = base + k * 256;
            if (e < 24000) base_accum<100>(p2, e, bacc, sacc);
        }
    }

    // block reduce 2 values
    const int lane = tid & 31, w = tid >> 5;
    bacc = warp_sum(bacc); sacc = warp_sum(sacc);
    __shared__ float red[8][2];
    if (lane == 0) { red[w][0] = bacc; red[w][1] = sacc; }
    __syncthreads();
    if (tid == 0) {
        float b2 = 0, s2 = 0;
        #pragma unroll
        for (int i = 0; i < 8; i++) { b2 += red[i][0]; s2 += red[i][1]; }
        g_bpart[bid][0] = b2; g_bpart[bid][1] = s2;
    }

    // last-block final reduction
    __threadfence();
    __shared__ int is_last;
    if (tid == 0) is_last = (atomicAdd(&g_ticket, 1) == gridDim.x - 1);
    __syncthreads();
    if (!is_last) return;

    float vb[3] = {0, 0, 0}, vs[3] = {0, 0, 0};
    for (int i = tid; i < NBT; i += 256) {
        const int sc = (i >= NB0 + NB1) ? 2 : ((i >= NB0) ? 1 : 0);
        vb[sc] += g_bpart[i][0];
        vs[sc] += g_bpart[i][1];
    }
    float vc[3][5] = {};
    for (int i = tid; i < NCB; i += 256) {
        const int sc = i >> 4;
        #pragma unroll
        for (int q = 0; q < 5; q++) vc[sc][q] += g_cpart[i][q];
    }

    // reduce 21 values: warp_sum each, then thread 0 sums across the 8 warps
    float vals[21];
    #pragma unroll
    for (int sc = 0; sc < 3; sc++) {
        vals[sc * 7 + 0] = vb[sc];
        vals[sc * 7 + 1] = vs[sc];
        #pragma unroll
        for (int q = 0; q < 5; q++) vals[sc * 7 + 2 + q] = vc[sc][q];
    }
    __shared__ float fred[8][21];
    #pragma unroll
    for (int q = 0; q < 21; q++) {
        const float r = warp_sum(vals[q]);
        if (lane == 0) fred[w][q] = r;
    }
    __syncthreads();
    if (tid == 0) {
        float tot[21];
        #pragma unroll
        for (int q = 0; q < 21; q++) {
            float a = 0;
            #pragma unroll
            for (int i = 0; i < 8; i++) a += fred[i][q];
            tot[q] = a;
        }
        const int Wd[3] = {80, 40, 20};
        float total = 0.f;
        #pragma unroll
        for (int sc = 0; sc < 3; sc++) {
            const float bb = tot[sc * 7 + 0];
            const float ss = tot[sc * 7 + 1];
            const float bd = tot[sc * 7 + 2];
            const float osum = tot[sc * 7 + 3];
            const float nsub = tot[sc * 7 + 4];
            const float csum = tot[sc * 7 + 5];
            const float nobj = tot[sc * 7 + 6];
            const float cells = (float)(BB * Wd[sc] * Wd[sc] * 3);
            const float n_obj = nobj + 1e-6f;
            const float n_noobj = (cells - nobj) + 1e-6f;
            const float box_loss   = (bb + bd) / n_obj;
            const float obj_loss   = osum / n_obj;
            const float noobj_loss = (ss - nsub) / n_noobj;
            const float cls_loss   = csum / n_obj;
            total += 0.05f * box_loss + 1.5f * (obj_loss + 0.5f * noobj_loss)
                   + 0.15f * cls_loss;
        }
        out[0] = total;
        g_ticket = 0;   // reset for next replay (deterministic)
    }
}

extern "C" void kernel_launch(void* const* d_in, const int* in_sizes, int n_in,
                              void* d_out, int out_size) {
    const float* p0 = (const float*)d_in[0];
    const float* p1 = (const float*)d_in[1];
    const float* p2 = (const float*)d_in[2];
    const float* tg = (const float*)d_in[3];
    float* out = (float*)d_out;

    prep_corr_kernel<<<NCB, 512>>>(p0, p1, p2, tg);
    base_fin_kernel<<<NBT, 256>>>(p0, p1, p2, out);
}